// round 9
// baseline (speedup 1.0000x reference)
#include <cuda_runtime.h>

#define BB 4
#define NT 256
#define NZ 384
#define NXX 384
#define NREC 128
#define DTc 0.001f
#define DHc 10.0f

#define NBLK 128
#define BLK_PER_B (NBLK / BB)      // 32 blocks per batch
#define ROWS 12                    // owned rows per block
#define RPT 6                      // rows per thread (2 halves)
#define NTHR (2 * NXX)             // 768 threads: thread = (column x, half)

// Packed halo word: hi32 = step counter (t+1 when u(t) published), lo32 = value.
// Single-word atomicity of the 64-bit access IS the synchronization; WAR on slot
// reuse is protected by the publish->consume data-dependency chain (hNb feeds the
// published boundary value).
__device__ unsigned long long d_pack[2][NBLK][2][NXX];

__global__ void zero_kernel() {
    const int n = 2 * NBLK * 2 * NXX;
    for (int i = blockIdx.x * blockDim.x + threadIdx.x; i < n;
         i += gridDim.x * blockDim.x)
        ((unsigned long long*)d_pack)[i] = 0ull;
}

__device__ __forceinline__ unsigned long long ld_vol_u64(
        const unsigned long long* p) {
    unsigned long long v;
    asm volatile("ld.volatile.global.u64 %0, [%1];" : "=l"(v) : "l"(p));
    return v;
}
__device__ __forceinline__ void st_vol_u64(unsigned long long* p,
                                           unsigned long long v) {
    asm volatile("st.volatile.global.u64 [%0], %1;" :: "l"(p), "l"(v));
}

__global__ __launch_bounds__(NTHR, 1) void wave_kernel(
    const float* __restrict__ xsrc,   // [B, NT]
    const float* __restrict__ vp,     // [NZ, NX]
    const int*   __restrict__ src_y,
    const int*   __restrict__ src_x,
    const int*   __restrict__ rec_y,
    const int*   __restrict__ rec_x,
    float*       __restrict__ out)    // [NT, B, NREC]
{
    __shared__ float sb0[ROWS * NXX];
    __shared__ float sb1[ROWS * NXX];

    const int tid  = threadIdx.x;
    const int x    = tid % NXX;
    const int half = tid / NXX;             // warp-uniform
    const int blk  = blockIdx.x;
    const int b    = blk / BLK_PER_B;
    const int bib  = blk % BLK_PER_B;
    const int z0   = bib * ROWS;
    const int rowbase = half * RPT;
    const float inv_dh2 = 1.0f / (DHc * DHc);

    const int topBlk = (bib > 0) ? blk - 1 : -1;
    const int botBlk = (bib < BLK_PER_B - 1) ? blk + 1 : -1;
    const int nb     = (half == 0) ? topBlk : botBlk;     // outward neighbor
    const bool hasNb = (nb >= 0);

    const int sy = src_y[b];
    const int sx = src_x[b];

    float ucur[RPT], uprev[RPT], csc[RPT], srcf[RPT];

#pragma unroll
    for (int k = 0; k < RPT; k++) {
        const int zg = z0 + rowbase + k;
        ucur[k]  = 0.0f;
        uprev[k] = 0.0f;
        const float c = vp[zg * NXX + x] * DTc;
        const bool lok = (x > 0 && x < NXX - 1 && zg > 0 && zg < NZ - 1);
        csc[k]  = lok ? (c * c * inv_dh2) : 0.0f;
        srcf[k] = (zg == sy && x == sx) ? 1.0f : 0.0f;
        sb0[(rowbase + k) * NXX + x] = 0.0f;
        sb1[(rowbase + k) * NXX + x] = 0.0f;
    }

    int rmine = 0, roff = 0;
    float* outp = out;
    if (tid < NREC) {
        const int ry = rec_y[tid];
        const int rx = rec_x[tid];
        rmine = (ry >= z0 && ry < z0 + ROWS);
        roff  = (ry - z0) * NXX + rx;
        outp  = out + b * NREC + tid;
    }
    const float* xs = xsrc + b * NT;

    const int pbase = rowbase * NXX + x;
    const int pL    = pbase - ((x > 0) ? 1 : 0);        // clamped left base
    const int pR    = pbase + ((x < NXX - 1) ? 1 : 0);  // clamped right base
    const int bk    = (half == 0) ? 0 : RPT - 1;        // my boundary slot

    unsigned long long* pub0  = &d_pack[0][blk][half][x];
    unsigned long long* pub1  = &d_pack[1][blk][half][x];
    const unsigned long long* pol0 = hasNb ? &d_pack[0][nb][half ^ 1][x] : pub0;
    const unsigned long long* pol1 = hasNb ? &d_pack[1][nb][half ^ 1][x] : pub1;

    float hNb = 0.0f;                      // neighbor boundary u(t-1)
    unsigned long long spec = 0ull;        // in-flight speculative poll result

    __syncthreads();

    // One step. POLC = slot (t-1)&1 (consume neighbor u(t-1), counter >= t),
    //           POLN = slot t&1     (speculative poll for neighbor u(t)).
    #define STEP(T, RBUF, WBUF, PUBP, POLC, POLN)                               \
    {                                                                           \
        const int   t  = (T);                                                   \
        const float xt = xs[t];                                                 \
        /* consume last step's spec: neighbor u(t-1); usually already valid */  \
        if (hasNb && t > 0) {                                                   \
            unsigned long long v = spec;                                        \
            while ((int)(v >> 32) < t) {                                        \
                __nanosleep(40);                                                \
                v = ld_vol_u64(POLC);                                           \
            }                                                                   \
            hNb = __uint_as_float((unsigned)v);                                 \
        }                                                                       \
        /* receiver gather for step t-1 (RBUF holds u(t-1)) */                  \
        if (t > 0 && rmine) { outp[(t - 1) * (BB * NREC)] = RBUF[roff]; }       \
        /* Phase 1: boundary row u(t); publish immediately */                   \
        const float bOld = ucur[bk];                                            \
        {                                                                       \
            const float inner = (half == 0) ? ucur[1] : ucur[RPT - 2];          \
            const float lap = hNb + inner + RBUF[pL + bk * NXX]                 \
                              + RBUF[pR + bk * NXX] - 4.0f * bOld;              \
            float hn = fmaf(csc[bk], lap, 2.0f * bOld - uprev[bk]);             \
            hn = fmaf(srcf[bk], xt, hn);                                        \
            uprev[bk] = bOld;                                                   \
            ucur[bk]  = hn;                                                     \
            WBUF[pbase + bk * NXX] = hn;                                        \
            if (hasNb) {                                                        \
                const unsigned long long pk =                                   \
                    ((unsigned long long)(unsigned)(t + 1) << 32) |             \
                    (unsigned long long)__float_as_uint(hn);                    \
                st_vol_u64(PUBP, pk);                                           \
            }                                                                   \
        }                                                                       \
        /* speculative poll for neighbor u(t); checked NEXT step (post-bar) */  \
        if (hasNb && t < NT - 1) spec = ld_vol_u64(POLN);                       \
        /* Phase 2: interior rows (old-value carry; branchless) */              \
        if (half == 0) {                                                        \
            float carry = bOld;                                                 \
            _Pragma("unroll")                                                   \
            for (int k = 1; k < RPT; k++) {                                     \
                const float uk = ucur[k];                                       \
                const float dn = (k < RPT - 1) ? ucur[k + 1]                    \
                                               : RBUF[pbase + RPT * NXX];       \
                const float lap = carry + dn + RBUF[pL + k * NXX]               \
                                  + RBUF[pR + k * NXX] - 4.0f * uk;             \
                float hn = fmaf(csc[k], lap, 2.0f * uk - uprev[k]);             \
                hn = fmaf(srcf[k], xt, hn);                                     \
                uprev[k] = uk;                                                  \
                ucur[k]  = hn;                                                  \
                WBUF[pbase + k * NXX] = hn;                                     \
                carry = uk;                                                     \
            }                                                                   \
        } else {                                                                \
            float carry = RBUF[pbase - NXX];                                    \
            _Pragma("unroll")                                                   \
            for (int k = 0; k < RPT - 1; k++) {                                 \
                const float uk = ucur[k];                                       \
                const float dn = (k < RPT - 2) ? ucur[k + 1] : bOld;            \
                const float lap = carry + dn + RBUF[pL + k * NXX]               \
                                  + RBUF[pR + k * NXX] - 4.0f * uk;             \
                float hn = fmaf(csc[k], lap, 2.0f * uk - uprev[k]);             \
                hn = fmaf(srcf[k], xt, hn);                                     \
                uprev[k] = uk;                                                  \
                ucur[k]  = hn;                                                  \
                WBUF[pbase + k * NXX] = hn;                                     \
                carry = uk;                                                     \
            }                                                                   \
        }                                                                       \
        __syncthreads();                                                        \
    }

#pragma unroll 1
    for (int tt = 0; tt < NT; tt += 2) {
        STEP(tt,     sb0, sb1, pub0, pol1, pol0)   // even t: publish slot 0
        STEP(tt + 1, sb1, sb0, pub1, pol0, pol1)   // odd  t: publish slot 1
    }
    #undef STEP

    // final receiver gather for t = NT-1 (last wbuf = sb0 since NT even)
    if (rmine)
        outp[(NT - 1) * (BB * NREC)] = sb0[roff];
}

extern "C" void kernel_launch(void* const* d_in, const int* in_sizes, int n_in,
                              void* d_out, int out_size)
{
    const float* xsrc  = (const float*)d_in[0];
    const float* vp    = (const float*)d_in[1];
    const int*   src_y = (const int*)d_in[2];
    const int*   src_x = (const int*)d_in[3];
    const int*   rec_y = (const int*)d_in[4];
    const int*   rec_x = (const int*)d_in[5];
    float*       out   = (float*)d_out;

    zero_kernel<<<128, 512>>>();
    wave_kernel<<<NBLK, NTHR>>>(xsrc, vp, src_y, src_x, rec_y, rec_x, out);
}

// round 10
// speedup vs baseline: 1.1479x; 1.1479x over previous
#include <cuda_runtime.h>

#define BB 4
#define NT 256
#define NZ 384
#define NXX 384
#define NREC 128
#define DTc 0.001f
#define DHc 10.0f

#define NBLK 128
#define BLK_PER_B (NBLK / BB)      // 32 blocks per batch
#define ROWS 12                    // owned rows per block
#define NPAIR (NXX / 2)            // 192 column pairs
#define NGRP 4                     // row groups
#define RPT 3                      // rows per thread
#define NTHR (NPAIR * NGRP)        // 768 threads

// Packed halo word: hi32 = step counter (t+1 when u(t) published), lo32 = value.
// Single-word atomicity of the 64-bit access IS the synchronization; WAR on slot
// reuse is protected by the publish->consume data-dependency chain.
__device__ unsigned long long d_pack[2][NBLK][2][NXX];
#define SLOT_OFF (NBLK * 2 * NXX)   // u64 elements between slot 0 and slot 1

__global__ void zero_kernel() {
    const int n = 2 * NBLK * 2 * NXX;
    for (int i = blockIdx.x * blockDim.x + threadIdx.x; i < n;
         i += gridDim.x * blockDim.x)
        ((unsigned long long*)d_pack)[i] = 0ull;
}

__device__ __forceinline__ unsigned long long ld_vol_u64(
        const unsigned long long* p) {
    unsigned long long v;
    asm volatile("ld.volatile.global.u64 %0, [%1];" : "=l"(v) : "l"(p));
    return v;
}
__device__ __forceinline__ void st_vol_u64(unsigned long long* p,
                                           unsigned long long v) {
    asm volatile("st.volatile.global.u64 [%0], %1;" :: "l"(p), "l"(v));
}

__global__ __launch_bounds__(NTHR, 1) void wave_kernel(
    const float* __restrict__ xsrc,   // [B, NT]
    const float* __restrict__ vp,     // [NZ, NX]
    const int*   __restrict__ src_y,
    const int*   __restrict__ src_x,
    const int*   __restrict__ rec_y,
    const int*   __restrict__ rec_x,
    float*       __restrict__ out)    // [NT, B, NREC]
{
    __shared__ float sb0[ROWS * NXX];
    __shared__ float sb1[ROWS * NXX];

    const int tid = threadIdx.x;
    const int p   = tid % NPAIR;            // column pair
    const int g   = tid / NPAIR;            // row group (warp-uniform: 6 warps/grp)
    const int x0  = 2 * p;
    const int x1  = x0 + 1;
    const int blk = blockIdx.x;
    const int b   = blk / BLK_PER_B;
    const int bib = blk % BLK_PER_B;
    const int z0  = bib * ROWS;
    const int rowbase = g * RPT;
    const float inv_dh2 = 1.0f / (DHc * DHc);

    const int topBlk = (bib > 0) ? blk - 1 : -1;
    const int botBlk = (bib < BLK_PER_B - 1) ? blk + 1 : -1;
    const bool isTop = (g == 0);
    const bool isBot = (g == NGRP - 1);
    const int  nb    = isTop ? topBlk : (isBot ? botBlk : -1);
    const bool hasNb = (nb >= 0);
    const int  side  = isTop ? 0 : 1;

    const int sy = src_y[b];
    const int sx = src_x[b];

    float ucA[RPT], ucB[RPT], pvA[RPT], pvB[RPT], csA[RPT], csB[RPT];
    unsigned smA = 0, smB = 0;              // source masks per column

#pragma unroll
    for (int k = 0; k < RPT; k++) {
        const int zg = z0 + rowbase + k;
        ucA[k] = 0.0f; ucB[k] = 0.0f;
        pvA[k] = 0.0f; pvB[k] = 0.0f;
        const float cA = vp[zg * NXX + x0] * DTc;
        const float cB = vp[zg * NXX + x1] * DTc;
        const bool zok = (zg > 0 && zg < NZ - 1);
        csA[k] = (zok && x0 > 0)       ? (cA * cA * inv_dh2) : 0.0f;
        csB[k] = (zok && x1 < NXX - 1) ? (cB * cB * inv_dh2) : 0.0f;
        if (zg == sy && x0 == sx) smA |= (1u << k);
        if (zg == sy && x1 == sx) smB |= (1u << k);
        sb0[(rowbase + k) * NXX + x0] = 0.0f;
        sb0[(rowbase + k) * NXX + x1] = 0.0f;
        sb1[(rowbase + k) * NXX + x0] = 0.0f;
        sb1[(rowbase + k) * NXX + x1] = 0.0f;
    }

    int rmine = 0, roff = 0;
    float* outp = out;
    if (tid < NREC) {
        const int ry = rec_y[tid];
        const int rx = rec_x[tid];
        rmine = (ry >= z0 && ry < z0 + ROWS);
        roff  = (ry - z0) * NXX + rx;
        outp  = out + b * NREC + tid;
    }
    const float* xs = xsrc + b * NT;

    const int pbase = rowbase * NXX + x0;
    const int dxl   = (x0 > 0) ? 1 : 0;            // clamped (csc=0 at edges)
    const int dxr   = (x1 < NXX - 1) ? 1 : 0;

    // handshake base pointers, slot 0 (slot 1 = +SLOT_OFF, folded to imm)
    unsigned long long* pubA = &d_pack[0][blk][side][x0];
    const unsigned long long* polA =
        hasNb ? &d_pack[0][nb][side ^ 1][x0] : pubA;

    float hNbA = 0.0f, hNbB = 0.0f;         // neighbor boundary u(t-1)

    __syncthreads();

    // one row of the pair: up/dn explicit, left/right from smem+regs
    #define DO_ROW(k, upA_, upB_, dnA_, dnB_, RBUF, WBUF, xt)                   \
    {                                                                           \
        const int pr = pbase + (k) * NXX;                                       \
        const float uA = ucA[k], uB = ucB[k];                                   \
        const float Lv = RBUF[pr - dxl];                                        \
        const float Rv = RBUF[pr + 1 + dxr];                                    \
        const float lapA = (upA_) + (dnA_) + Lv + uB - 4.0f * uA;               \
        const float lapB = (upB_) + (dnB_) + uA + Rv - 4.0f * uB;               \
        float hA = fmaf(csA[k], lapA, 2.0f * uA - pvA[k]);                      \
        float hB = fmaf(csB[k], lapB, 2.0f * uB - pvB[k]);                      \
        if (smA & (1u << (k))) hA += xt;                                        \
        if (smB & (1u << (k))) hB += xt;                                        \
        pvA[k] = uA; pvB[k] = uB;                                               \
        ucA[k] = hA; ucB[k] = hB;                                               \
        *(float2*)&WBUF[pr] = make_float2(hA, hB);                              \
    }

    #define STEP(T, RBUF, WBUF, SOFF)                                           \
    {                                                                           \
        const int   t  = (T);                                                   \
        const float xt = xs[t];                                                 \
        if (t > 0 && rmine) { outp[(t - 1) * (BB * NREC)] = RBUF[roff]; }       \
        /* old values (pre-update) needed as vertical neighbors */              \
        const float a0 = ucA[0], b0 = ucB[0];                                   \
        const float a1 = ucA[1], b1 = ucB[1];                                   \
        const float a2 = ucA[2], b2 = ucB[2];                                   \
        unsigned long long specA = 0ull, specB = 0ull;                          \
        if (isTop) {                                                            \
            /* boundary row k=0: publish immediately */                         \
            DO_ROW(0, hNbA, hNbB, a1, b1, RBUF, WBUF, xt);                      \
            if (hasNb) {                                                        \
                const unsigned long long hi =                                   \
                    (unsigned long long)(unsigned)(t + 1) << 32;                \
                st_vol_u64(pubA + (SOFF),     hi | __float_as_uint(ucA[0]));    \
                st_vol_u64(pubA + (SOFF) + 1, hi | __float_as_uint(ucB[0]));    \
                if (t < NT - 1) {                                               \
                    specA = ld_vol_u64(polA + (SOFF));                          \
                    specB = ld_vol_u64(polA + (SOFF) + 1);                      \
                }                                                               \
            }                                                                   \
            DO_ROW(1, a0, b0, a2, b2, RBUF, WBUF, xt);                          \
            const float2 dn = *(const float2*)&RBUF[pbase + RPT * NXX];         \
            DO_ROW(2, a1, b1, dn.x, dn.y, RBUF, WBUF, xt);                      \
        } else if (isBot) {                                                     \
            /* boundary row k=2: publish immediately */                         \
            DO_ROW(2, a1, b1, hNbA, hNbB, RBUF, WBUF, xt);                      \
            if (hasNb) {                                                        \
                const unsigned long long hi =                                   \
                    (unsigned long long)(unsigned)(t + 1) << 32;                \
                st_vol_u64(pubA + (SOFF),     hi | __float_as_uint(ucA[2]));    \
                st_vol_u64(pubA + (SOFF) + 1, hi | __float_as_uint(ucB[2]));    \
                if (t < NT - 1) {                                               \
                    specA = ld_vol_u64(polA + (SOFF));                          \
                    specB = ld_vol_u64(polA + (SOFF) + 1);                      \
                }                                                               \
            }                                                                   \
            const float2 up = *(const float2*)&RBUF[pbase - NXX];               \
            DO_ROW(0, up.x, up.y, a1, b1, RBUF, WBUF, xt);                      \
            DO_ROW(1, a0, b0, a2, b2, RBUF, WBUF, xt);                          \
        } else {                                                                \
            const float2 up = *(const float2*)&RBUF[pbase - NXX];               \
            DO_ROW(0, up.x, up.y, a1, b1, RBUF, WBUF, xt);                      \
            DO_ROW(1, a0, b0, a2, b2, RBUF, WBUF, xt);                          \
            const float2 dn = *(const float2*)&RBUF[pbase + RPT * NXX];         \
            DO_ROW(2, a1, b1, dn.x, dn.y, RBUF, WBUF, xt);                      \
        }                                                                       \
        /* consume speculative poll (usually already valid) */                  \
        if (hasNb && t < NT - 1) {                                              \
            unsigned long long vA = specA, vB = specB;                          \
            while ((int)(vA >> 32) < t + 1) vA = ld_vol_u64(polA + (SOFF));     \
            while ((int)(vB >> 32) < t + 1) vB = ld_vol_u64(polA + (SOFF) + 1); \
            hNbA = __uint_as_float((unsigned)vA);                               \
            hNbB = __uint_as_float((unsigned)vB);                               \
        }                                                                       \
        __syncthreads();                                                        \
    }

#pragma unroll 1
    for (int tt = 0; tt < NT; tt += 2) {
        STEP(tt,     sb0, sb1, 0)          // even t: slot 0
        STEP(tt + 1, sb1, sb0, SLOT_OFF)   // odd  t: slot 1
    }
    #undef STEP
    #undef DO_ROW

    // final receiver gather for t = NT-1 (last wbuf = sb0 since NT even)
    if (rmine)
        outp[(NT - 1) * (BB * NREC)] = sb0[roff];
}

extern "C" void kernel_launch(void* const* d_in, const int* in_sizes, int n_in,
                              void* d_out, int out_size)
{
    const float* xsrc  = (const float*)d_in[0];
    const float* vp    = (const float*)d_in[1];
    const int*   src_y = (const int*)d_in[2];
    const int*   src_x = (const int*)d_in[3];
    const int*   rec_y = (const int*)d_in[4];
    const int*   rec_x = (const int*)d_in[5];
    float*       out   = (float*)d_out;

    zero_kernel<<<128, 512>>>();
    wave_kernel<<<NBLK, NTHR>>>(xsrc, vp, src_y, src_x, rec_y, rec_x, out);
}